// round 3
// baseline (speedup 1.0000x reference)
#include <cuda_runtime.h>
#include <math.h>

#define BB 4
#define NN 4096
#define DKK 64
#define MT 20                       // Fourier modes
#define THALF 8.0
#define OMEGA1 0.39269908169872414f // pi/8
#define TILE 64
#define NBLK 256                    // BB*NN/TILE
#define FSTR 132                    // per-mode row: C[64], S[64], cc, ss, pad2
#define FLEN (MT*FSTR)              // 2640

struct CoefArg { float a[MT]; };

__device__ __align__(16) float g_Wvt[DKK*DKK];
__device__ __align__(16) float g_Q[BB*NN];
__device__ __align__(16) float g_part[(size_t)NBLK*FLEN];
__device__ __align__(16) float g_feat[BB*FLEN];

// ---------------------------------------------------------------------------
// K0: transpose Wv (once) -> g_Wvt[d*64+e] = Wv[e*64+d]
// ---------------------------------------------------------------------------
__global__ __launch_bounds__(256) void k_prep(const float* __restrict__ Wv)
{
    int i = blockIdx.x * 256 + threadIdx.x;   // i = e*64 + d
    g_Wvt[(i & 63) * DKK + (i >> 6)] = Wv[i];
}

// ---------------------------------------------------------------------------
// K1: per-tile QKV + Fourier feature partial sums. grid=256, block=256.
// ---------------------------------------------------------------------------
__global__ __launch_bounds__(256) void k_main(
    const float* __restrict__ x, const float* __restrict__ bv,
    const float* __restrict__ wq, const float* __restrict__ wk)
{
    extern __shared__ float sm[];
    float* xs  = sm;                 // 64*65  = 4160
    float* Wvt = xs  + TILE*65;      // 64*68  = 4352
    float* Vs  = Wvt + 64*68;        // 64*68  = 4352
    float* cs2 = Vs  + TILE*68;      // 20*132 = 2640 (interleaved c,s per mode/token)
    float* wqs = cs2 + MT*132;       // 64
    float* wks = wqs + 64;           // 64
    float* bvs = wks + 64;           // 64
    // combine scratch overlays xs..Vs (dead by then): 4 partials * 2560 floats

    const int t = threadIdx.x;
    const int blk = blockIdx.x;
    const float* xt = x + (size_t)blk * TILE * DKK;

    // -- Phase A: stage --
    #pragma unroll
    for (int it = 0; it < 16; it++) {
        int i = it*256 + t;
        xs[(i >> 6)*65 + (i & 63)] = xt[i];
        Wvt[(i >> 6)*68 + (i & 63)] = g_Wvt[i];
    }
    if (t < DKK) { wqs[t] = wq[t]; wks[t] = wk[t]; bvs[t] = bv[t]; }
    __syncthreads();

    const int j = t >> 2, p = t & 3;

    // -- Phase B: Q,K scalars (quad-split) + mode table (4 lanes x 5 modes) --
    {
        float q = 0.f, k = 0.f;
        const float* xr = xs + j*65 + p*16;
        #pragma unroll
        for (int d = 0; d < 16; d++) {
            q = fmaf(xr[d], wqs[p*16 + d], q);
            k = fmaf(xr[d], wks[p*16 + d], k);
        }
        q += __shfl_xor_sync(0xffffffffu, q, 1);
        q += __shfl_xor_sync(0xffffffffu, q, 2);
        k += __shfl_xor_sync(0xffffffffu, k, 1);
        k += __shfl_xor_sync(0xffffffffu, k, 2);
        if (p == 0) g_Q[(size_t)blk*TILE + j] = q;
        float th = OMEGA1 * k;
        float s1, c1; __sincosf(th, &s1, &c1);
        float s0, c0; sincosf(5.f * (float)p * th, &s0, &c0);  // accurate start
        #pragma unroll
        for (int mi = 0; mi < 5; mi++) {
            int m = 5*p + mi;
            cs2[m*132 + 2*j]     = c0;
            cs2[m*132 + 2*j + 1] = s0;
            float cn = c0*c1 - s0*s1;
            s0 = fmaf(s0, c1, c0*s1);
            c0 = cn;
        }
    }

    // -- Phase C: V = x @ Wv^T + bv  (thread = (token j, quarter p): 16 outs) --
    {
        float acc[16];
        #pragma unroll
        for (int i = 0; i < 16; i++) acc[i] = bvs[p*16 + i];
        #pragma unroll 4
        for (int d2 = 0; d2 < DKK; d2++) {
            float xv = xs[j*65 + d2];
            const float4* wrow = (const float4*)&Wvt[d2*68 + p*16];
            #pragma unroll
            for (int i4 = 0; i4 < 4; i4++) {
                float4 w4 = wrow[i4];
                acc[i4*4+0] = fmaf(xv, w4.x, acc[i4*4+0]);
                acc[i4*4+1] = fmaf(xv, w4.y, acc[i4*4+1]);
                acc[i4*4+2] = fmaf(xv, w4.z, acc[i4*4+2]);
                acc[i4*4+3] = fmaf(xv, w4.w, acc[i4*4+3]);
            }
        }
        float4* vrow = (float4*)&Vs[j*68 + p*16];
        #pragma unroll
        for (int i4 = 0; i4 < 4; i4++)
            vrow[i4] = make_float4(acc[i4*4+0], acc[i4*4+1], acc[i4*4+2], acc[i4*4+3]);
    }
    __syncthreads();

    // -- Phase D: rank update. warp w -> tokens [8w,8w+8); lane owns dims (l, l+32),
    //    all 20 modes register-resident. --
    const int w = t >> 5, l = t & 31;
    float2 aC[MT], aS[MT];
    #pragma unroll
    for (int m = 0; m < MT; m++) { aC[m] = make_float2(0.f,0.f); aS[m] = make_float2(0.f,0.f); }
    #pragma unroll 2
    for (int jj = 0; jj < 8; jj++) {
        int jt = w*8 + jj;
        float vx = Vs[jt*68 + l];
        float vy = Vs[jt*68 + 32 + l];
        #pragma unroll
        for (int m = 0; m < MT; m++) {
            float2 cspair = *(const float2*)&cs2[m*132 + 2*jt];  // broadcast
            aC[m].x = fmaf(cspair.x, vx, aC[m].x);
            aC[m].y = fmaf(cspair.x, vy, aC[m].y);
            aS[m].x = fmaf(cspair.y, vx, aS[m].x);
            aS[m].y = fmaf(cspair.y, vy, aS[m].y);
        }
    }

    // -- Phase E: combine 8 warp-partials via smem tree (scratch overlays xs..Vs) --
    float* scr = sm;   // 4 partials x (20 modes x 128) floats = 10240 < 12864
    #pragma unroll
    for (int step = 4; step >= 1; step >>= 1) {
        __syncthreads();
        if (w >= step && w < 2*step) {
            float* dst = scr + (w - step) * (MT*128);
            #pragma unroll
            for (int m = 0; m < MT; m++) {
                dst[m*128 + l]       = aC[m].x;
                dst[m*128 + 32 + l]  = aC[m].y;
                dst[m*128 + 64 + l]  = aS[m].x;
                dst[m*128 + 96 + l]  = aS[m].y;
            }
        }
        __syncthreads();
        if (w < step) {
            const float* src = scr + w * (MT*128);
            #pragma unroll
            for (int m = 0; m < MT; m++) {
                aC[m].x += src[m*128 + l];
                aC[m].y += src[m*128 + 32 + l];
                aS[m].x += src[m*128 + 64 + l];
                aS[m].y += src[m*128 + 96 + l];
            }
        }
    }

    // final write: warp 0 holds full block partial
    float* pp = g_part + (size_t)blk * FLEN;
    if (w == 0) {
        #pragma unroll
        for (int m = 0; m < MT; m++) {
            pp[m*FSTR + l]          = aC[m].x;
            pp[m*FSTR + 32 + l]     = aC[m].y;
            pp[m*FSTR + 64 + l]     = aS[m].x;
            pp[m*FSTR + 96 + l]     = aS[m].y;
        }
    }
    // cc/ss per mode from the (intact) table: threads 0..19
    if (t < MT) {
        float cc = 0.f, ss = 0.f;
        #pragma unroll 8
        for (int jt = 0; jt < TILE; jt++) {
            float2 cspair = *(const float2*)&cs2[t*132 + 2*jt];
            cc += cspair.x; ss += cspair.y;
        }
        pp[t*FSTR + 128] = cc;
        pp[t*FSTR + 129] = ss;
    }
}

// ---------------------------------------------------------------------------
// K2: reduce 64 tile-partials per batch (deterministic)
// ---------------------------------------------------------------------------
__global__ __launch_bounds__(256) void k_red()
{
    int f = blockIdx.x * 256 + threadIdx.x;
    int b = blockIdx.y;
    if (f >= FLEN) return;
    float s = 0.f;
    #pragma unroll 8
    for (int tb = 0; tb < 64; tb++)
        s += g_part[(size_t)(b*64 + tb)*FLEN + f];
    g_feat[b*FLEN + f] = s;
}

// ---------------------------------------------------------------------------
// K3: per-token output + residual + LayerNorm. grid=256, block=256 (4 thr/token)
// ---------------------------------------------------------------------------
__global__ __launch_bounds__(256) void k_out(
    const float* __restrict__ x, const float* __restrict__ gamma,
    const float* __restrict__ beta, float* __restrict__ out, CoefArg ca)
{
    extern __shared__ float sm[];
    float* fs = sm;            // FLEN
    float* gs = fs + FLEN;     // 64
    float* bs = gs + 64;       // 64

    const int t = threadIdx.x;
    const int blk = blockIdx.x;
    const int b = blk >> 6;

    for (int i = t; i < FLEN; i += 256) fs[i] = g_feat[b*FLEN + i];
    if (t < DKK) { gs[t] = gamma[t]; bs[t] = beta[t]; }
    __syncthreads();

    const int j = t >> 2, p = t & 3;
    const size_t tok = (size_t)blk*TILE + j;

    float q = g_Q[tok];
    float s1, c1; __sincosf(OMEGA1 * q, &s1, &c1);
    float c = 1.f, s = 0.f;

    float num[16];
    #pragma unroll
    for (int k = 0; k < 16; k++) num[k] = 0.f;
    float den = 0.f;

    #pragma unroll 4
    for (int m = 0; m < MT; m++) {
        float wc = ca.a[m] * c;
        float ws = ca.a[m] * s;
        const float* bse = fs + m*FSTR;
        den = fmaf(wc, bse[128], fmaf(ws, bse[129], den));
        const float4* C4 = (const float4*)&bse[p*16];
        const float4* S4 = (const float4*)&bse[64 + p*16];
        #pragma unroll
        for (int k4 = 0; k4 < 4; k4++) {
            float4 C = C4[k4];
            float4 S = S4[k4];
            num[k4*4+0] = fmaf(wc, C.x, fmaf(ws, S.x, num[k4*4+0]));
            num[k4*4+1] = fmaf(wc, C.y, fmaf(ws, S.y, num[k4*4+1]));
            num[k4*4+2] = fmaf(wc, C.z, fmaf(ws, S.z, num[k4*4+2]));
            num[k4*4+3] = fmaf(wc, C.w, fmaf(ws, S.w, num[k4*4+3]));
        }
        float cn = c*c1 - s*s1;
        s = fmaf(s, c1, c*s1);
        c = cn;
    }

    // out = num/den + x, then LayerNorm over the 4-lane quad
    const float* xr = x + tok*DKK + p*16;
    float invden = 1.f / den;
    float psum = 0.f;
    #pragma unroll
    for (int k = 0; k < 16; k++) {
        num[k] = fmaf(num[k], invden, xr[k]);
        psum += num[k];
    }
    psum += __shfl_xor_sync(0xffffffffu, psum, 1);
    psum += __shfl_xor_sync(0xffffffffu, psum, 2);
    float mu = psum * (1.f/64.f);
    float pvar = 0.f;
    #pragma unroll
    for (int k = 0; k < 16; k++) {
        float dd = num[k] - mu;
        pvar = fmaf(dd, dd, pvar);
    }
    pvar += __shfl_xor_sync(0xffffffffu, pvar, 1);
    pvar += __shfl_xor_sync(0xffffffffu, pvar, 2);
    float rstd = rsqrtf(pvar*(1.f/64.f) + 1e-5f);

    float* orow = out + tok*DKK + p*16;
    #pragma unroll
    for (int k = 0; k < 16; k++)
        orow[k] = (num[k] - mu) * rstd * gs[p*16 + k] + bs[p*16 + k];
}

// ---------------------------------------------------------------------------
extern "C" void kernel_launch(void* const* d_in, const int* in_sizes, int n_in,
                              void* d_out, int out_size)
{
    const float* x     = (const float*)d_in[0];
    const float* Wv    = (const float*)d_in[1];
    const float* bv    = (const float*)d_in[2];
    const float* wq    = (const float*)d_in[3];
    const float* wk    = (const float*)d_in[4];
    const float* gamma = (const float*)d_in[5];
    const float* beta  = (const float*)d_in[6];
    float* out = (float*)d_out;

    // Fourier cosine coefficients of g(t)=exp(exp(-t^2)/8), host double precision
    CoefArg ca;
    {
        const int P = 8192;
        const double T = THALF, L = 2.0*T;
        for (int m = 0; m < MT; m++) {
            double wm = 3.14159265358979323846 * (double)m / T;
            double sum = 0.0;
            for (int ip = 0; ip < P; ip++) {
                double tt = -T + (ip + 0.5) * (L / P);
                sum += exp(exp(-tt*tt) * 0.125) * cos(wm * tt);
            }
            ca.a[m] = (float)(((m == 0) ? 1.0 : 2.0) * sum / (double)P);
        }
    }

    const size_t sm1 = (size_t)(TILE*65 + 64*68 + TILE*68 + MT*132 + 3*64) * sizeof(float);
    const size_t sm2 = (size_t)(FLEN + 128) * sizeof(float);
    cudaFuncSetAttribute(k_main, cudaFuncAttributeMaxDynamicSharedMemorySize, (int)sm1);
    cudaFuncSetAttribute(k_out,  cudaFuncAttributeMaxDynamicSharedMemorySize, (int)sm2);

    k_prep<<<16, 256>>>(Wv);
    k_main<<<NBLK, 256, sm1>>>(x, bv, wq, wk);
    k_red<<<dim3((FLEN + 255)/256, BB), 256>>>();
    k_out<<<NBLK, 256, sm2>>>(x, gamma, beta, out, ca);
}

// round 4
// speedup vs baseline: 1.3159x; 1.3159x over previous
#include <cuda_runtime.h>
#include <math.h>

#define BB 4
#define NN 4096
#define DKK 64
#define MT 16                       // Fourier modes (power of 2; tail ~3e-5)
#define THALF 8.0
#define OMEGA1 0.39269908169872414f // pi/8
#define TILE 64
#define NBLK 256                    // BB*NN/TILE
#define FSTR 132                    // per-mode row: C[64], S[64], cc, ss, pad2
#define FLEN (MT*FSTR)              // 2112

struct CoefArg { float a[MT]; };

__device__ __align__(16) float g_Wvt[DKK*DKK];
__device__ __align__(16) float g_Q[BB*NN];
__device__ __align__(16) float g_part[(size_t)NBLK*FLEN];
__device__ __align__(16) float g_feat[BB*FLEN];

// ---------------------------------------------------------------------------
// K0: transpose Wv (once) -> g_Wvt[d*64+e] = Wv[e*64+d]
// ---------------------------------------------------------------------------
__global__ __launch_bounds__(256) void k_prep(const float* __restrict__ Wv)
{
    int i = blockIdx.x * 256 + threadIdx.x;   // i = e*64 + d
    g_Wvt[(i & 63) * DKK + (i >> 6)] = Wv[i];
}

// ---------------------------------------------------------------------------
// K1: per-tile QKV + Fourier feature partial sums. grid=256, block=256.
// smem ~59KB -> 3 CTAs/SM. Only 2 __syncthreads.
// ---------------------------------------------------------------------------
__global__ __launch_bounds__(256) void k_main(
    const float* __restrict__ x, const float* __restrict__ bv,
    const float* __restrict__ wq, const float* __restrict__ wk)
{
    extern __shared__ float sm[];
    float* xs  = sm;                 // 64*65  = 4160
    float* Wvt = xs  + TILE*65;      // 64*68  = 4352
    float* Vs  = Wvt + 64*68;        // 64*68  = 4352
    float* cs2 = Vs  + TILE*68;      // 16*132 = 2112 (interleaved c,s per mode)
    float* wqs = cs2 + MT*132;       // 64
    float* wks = wqs + 64;           // 64
    float* bvs = wks + 64;           // 64

    const int t = threadIdx.x;
    const int blk = blockIdx.x;
    const float* xt = x + (size_t)blk * TILE * DKK;

    // -- Phase A: stage (coalesced LDG, conflict-free STS) --
    #pragma unroll
    for (int it = 0; it < 16; it++) {
        int i = it*256 + t;
        xs[(i >> 6)*65 + (i & 63)] = xt[i];
        Wvt[(i >> 6)*68 + (i & 63)] = g_Wvt[i];
    }
    if (t < DKK) { wqs[t] = wq[t]; wks[t] = wk[t]; bvs[t] = bv[t]; }
    __syncthreads();

    const int j = t >> 2, p = t & 3;

    // -- Phase B: Q,K scalars (quad-split) + mode table (4 lanes x 4 modes) --
    {
        float q = 0.f, k = 0.f;
        const float* xr = xs + j*65 + p*16;
        #pragma unroll
        for (int d = 0; d < 16; d++) {
            q = fmaf(xr[d], wqs[p*16 + d], q);
            k = fmaf(xr[d], wks[p*16 + d], k);
        }
        q += __shfl_xor_sync(0xffffffffu, q, 1);
        q += __shfl_xor_sync(0xffffffffu, q, 2);
        k += __shfl_xor_sync(0xffffffffu, k, 1);
        k += __shfl_xor_sync(0xffffffffu, k, 2);
        if (p == 0) g_Q[(size_t)blk*TILE + j] = q;
        float th = OMEGA1 * k;
        float s1, c1; __sincosf(th, &s1, &c1);
        float s0, c0; __sincosf(4.f * (float)p * th, &s0, &c0);
        #pragma unroll
        for (int mi = 0; mi < 4; mi++) {
            int m = 4*p + mi;
            cs2[m*132 + 2*j]     = c0;
            cs2[m*132 + 2*j + 1] = s0;
            float cn = c0*c1 - s0*s1;
            s0 = fmaf(s0, c1, c0*s1);
            c0 = cn;
        }
    }
    // (no barrier needed: Phase C touches only xs/Wvt/Vs)

    // -- Phase C: V = x @ Wv^T + bv  (thread = (token j, quarter p): 16 outs) --
    {
        float acc[16];
        #pragma unroll
        for (int i = 0; i < 16; i++) acc[i] = bvs[p*16 + i];
        #pragma unroll 4
        for (int d2 = 0; d2 < DKK; d2++) {
            float xv = xs[j*65 + d2];
            const float4* wrow = (const float4*)&Wvt[d2*68 + p*16];
            #pragma unroll
            for (int i4 = 0; i4 < 4; i4++) {
                float4 w4 = wrow[i4];
                acc[i4*4+0] = fmaf(xv, w4.x, acc[i4*4+0]);
                acc[i4*4+1] = fmaf(xv, w4.y, acc[i4*4+1]);
                acc[i4*4+2] = fmaf(xv, w4.z, acc[i4*4+2]);
                acc[i4*4+3] = fmaf(xv, w4.w, acc[i4*4+3]);
            }
        }
        float4* vrow = (float4*)&Vs[j*68 + p*16];
        #pragma unroll
        for (int i4 = 0; i4 < 4; i4++)
            vrow[i4] = make_float4(acc[i4*4+0], acc[i4*4+1], acc[i4*4+2], acc[i4*4+3]);
    }
    __syncthreads();

    // -- Phase D: rank update. thread = (d4 = t&15, m = t>>4); owns its
    //    (4 dims x 1 mode) slice across ALL 64 tokens -> direct partial write,
    //    no cross-warp combine. 8 accumulator registers. --
    {
        const int d4 = t & 15, m = t >> 4;
        float aC0=0,aC1=0,aC2=0,aC3=0, aS0=0,aS1=0,aS2=0,aS3=0;
        float aCC=0.f, aSS=0.f;
        #pragma unroll 8
        for (int jt = 0; jt < TILE; jt++) {
            float4 v = *(const float4*)&Vs[jt*68 + d4*4];
            float2 cspair = *(const float2*)&cs2[m*132 + 2*jt];  // broadcast
            aC0 = fmaf(cspair.x, v.x, aC0); aC1 = fmaf(cspair.x, v.y, aC1);
            aC2 = fmaf(cspair.x, v.z, aC2); aC3 = fmaf(cspair.x, v.w, aC3);
            aS0 = fmaf(cspair.y, v.x, aS0); aS1 = fmaf(cspair.y, v.y, aS1);
            aS2 = fmaf(cspair.y, v.z, aS2); aS3 = fmaf(cspair.y, v.w, aS3);
            aCC += cspair.x; aSS += cspair.y;
        }
        float* bse = g_part + (size_t)blk * FLEN + m*FSTR;
        *(float4*)&bse[d4*4]      = make_float4(aC0, aC1, aC2, aC3);
        *(float4*)&bse[64 + d4*4] = make_float4(aS0, aS1, aS2, aS3);
        if (d4 == 0) { bse[128] = aCC; bse[129] = aSS; }
    }
}

// ---------------------------------------------------------------------------
// K2: reduce 64 tile-partials per batch (deterministic)
// ---------------------------------------------------------------------------
__global__ __launch_bounds__(256) void k_red()
{
    int f = blockIdx.x * 256 + threadIdx.x;
    int b = blockIdx.y;
    if (f >= FLEN) return;
    float s = 0.f;
    #pragma unroll 8
    for (int tb = 0; tb < 64; tb++)
        s += g_part[(size_t)(b*64 + tb)*FLEN + f];
    g_feat[b*FLEN + f] = s;
}

// ---------------------------------------------------------------------------
// K3: per-token output + residual + LayerNorm.
// grid=1024, block=256: 16 threads/token, 16 tokens/block. num[4]/thread.
// ---------------------------------------------------------------------------
__global__ __launch_bounds__(256) void k_out(
    const float* __restrict__ x, const float* __restrict__ gamma,
    const float* __restrict__ beta, float* __restrict__ out, CoefArg ca)
{
    extern __shared__ float sm[];
    float* fs = sm;            // FLEN = 2112
    float* gs = fs + FLEN;     // 64
    float* bs = gs + 64;       // 64

    const int t = threadIdx.x;
    const int blk = blockIdx.x;
    const int b = blk >> 8;    // 256 blocks per batch

    for (int i = t; i < FLEN; i += 256) fs[i] = g_feat[b*FLEN + i];
    if (t < DKK) { gs[t] = gamma[t]; bs[t] = beta[t]; }
    __syncthreads();

    const int p = t & 15;                       // dim quarter-of-quarter (4 dims)
    const size_t tok = (size_t)blk*16 + (t >> 4);

    float q = g_Q[tok];
    float s1, c1; __sincosf(OMEGA1 * q, &s1, &c1);
    float c = 1.f, s = 0.f;

    float4 num = make_float4(0.f, 0.f, 0.f, 0.f);
    float den = 0.f;

    #pragma unroll
    for (int m = 0; m < MT; m++) {
        float wc = ca.a[m] * c;
        float ws = ca.a[m] * s;
        const float* bse = fs + m*FSTR;
        den = fmaf(wc, bse[128], fmaf(ws, bse[129], den));
        float4 C = *(const float4*)&bse[p*4];
        float4 S = *(const float4*)&bse[64 + p*4];
        num.x = fmaf(wc, C.x, fmaf(ws, S.x, num.x));
        num.y = fmaf(wc, C.y, fmaf(ws, S.y, num.y));
        num.z = fmaf(wc, C.z, fmaf(ws, S.z, num.z));
        num.w = fmaf(wc, C.w, fmaf(ws, S.w, num.w));
        float cn = c*c1 - s*s1;
        s = fmaf(s, c1, c*s1);
        c = cn;
    }

    // out = num/den + x, then LayerNorm over the 16-lane token group
    float4 xr = *(const float4*)(x + tok*DKK + p*4);
    float invden = 1.f / den;
    num.x = fmaf(num.x, invden, xr.x);
    num.y = fmaf(num.y, invden, xr.y);
    num.z = fmaf(num.z, invden, xr.z);
    num.w = fmaf(num.w, invden, xr.w);

    float psum = num.x + num.y + num.z + num.w;
    psum += __shfl_xor_sync(0xffffffffu, psum, 1);
    psum += __shfl_xor_sync(0xffffffffu, psum, 2);
    psum += __shfl_xor_sync(0xffffffffu, psum, 4);
    psum += __shfl_xor_sync(0xffffffffu, psum, 8);
    float mu = psum * (1.f/64.f);

    float dx = num.x - mu, dy = num.y - mu, dz = num.z - mu, dw = num.w - mu;
    float pvar = dx*dx + dy*dy + dz*dz + dw*dw;
    pvar += __shfl_xor_sync(0xffffffffu, pvar, 1);
    pvar += __shfl_xor_sync(0xffffffffu, pvar, 2);
    pvar += __shfl_xor_sync(0xffffffffu, pvar, 4);
    pvar += __shfl_xor_sync(0xffffffffu, pvar, 8);
    float rstd = rsqrtf(pvar*(1.f/64.f) + 1e-5f);

    float4 g4 = *(const float4*)&gs[p*4];
    float4 b4 = *(const float4*)&bs[p*4];
    float4 o;
    o.x = dx * rstd * g4.x + b4.x;
    o.y = dy * rstd * g4.y + b4.y;
    o.z = dz * rstd * g4.z + b4.z;
    o.w = dw * rstd * g4.w + b4.w;
    *(float4*)(out + tok*DKK + p*4) = o;
}

// ---------------------------------------------------------------------------
extern "C" void kernel_launch(void* const* d_in, const int* in_sizes, int n_in,
                              void* d_out, int out_size)
{
    const float* x     = (const float*)d_in[0];
    const float* Wv    = (const float*)d_in[1];
    const float* bv    = (const float*)d_in[2];
    const float* wq    = (const float*)d_in[3];
    const float* wk    = (const float*)d_in[4];
    const float* gamma = (const float*)d_in[5];
    const float* beta  = (const float*)d_in[6];
    float* out = (float*)d_out;

    // Fourier cosine coefficients of g(t)=exp(exp(-t^2)/8), host double precision
    CoefArg ca;
    {
        const int P = 8192;
        const double T = THALF, L = 2.0*T;
        for (int m = 0; m < MT; m++) {
            double wm = 3.14159265358979323846 * (double)m / T;
            double sum = 0.0;
            for (int ip = 0; ip < P; ip++) {
                double tt = -T + (ip + 0.5) * (L / P);
                sum += exp(exp(-tt*tt) * 0.125) * cos(wm * tt);
            }
            ca.a[m] = (float)(((m == 0) ? 1.0 : 2.0) * sum / (double)P);
        }
    }

    const size_t sm1 = (size_t)(TILE*65 + 64*68 + TILE*68 + MT*132 + 3*64) * sizeof(float);
    const size_t sm2 = (size_t)(FLEN + 128) * sizeof(float);
    cudaFuncSetAttribute(k_main, cudaFuncAttributeMaxDynamicSharedMemorySize, (int)sm1);
    cudaFuncSetAttribute(k_out,  cudaFuncAttributeMaxDynamicSharedMemorySize, (int)sm2);

    k_prep<<<16, 256>>>(Wv);
    k_main<<<NBLK, 256, sm1>>>(x, bv, wq, wk);
    k_red<<<dim3((FLEN + 255)/256, BB), 256>>>();
    k_out<<<1024, 256, sm2>>>(x, gamma, beta, out, ca);
}